// round 1
// baseline (speedup 1.0000x reference)
#include <cuda_runtime.h>
#include <cuda_bf16.h>
#include <cstdint>

// Problem constants
#define CC 8
#define KK 64
#define DD 32
#define NN 2048

// Packed per-(c,k) weight block layout (floats)
#define PK      4352
#define O_W1S   0      // [64][16]  W1s columns at masked dims
#define O_B1S   1024   // [64]
#define O_W2S   1088   // [64][16]  W2s transposed: [j][i] = W2[ud(i)][j]
#define O_B2S   2112   // [16]
#define O_W1T   2128
#define O_B1T   3152
#define O_W2T   3216
#define O_B2T   4240
#define O_ANE   4256   // [32] exp(-an_s)
#define O_ANT   4288   // [32] an_t
#define O_ASUM  4320   // sum(an_s)

// Scratch (__device__ globals: allocation-free)
__device__ float g_packed[CC * KK * PK];   // ~8.9 MB
__device__ float g_logq[CC * NN];
__device__ float g_E[NN * CC];             // [n][c]
__device__ float g_G[NN * CC];
__device__ float g_A[NN * CC];
__device__ float g_den[CC];
__device__ float g_S[CC * CC];

// ---------------------------------------------------------------------------
// cp.async helpers
// ---------------------------------------------------------------------------
__device__ __forceinline__ void cp_async16(void* smem, const void* gmem) {
    unsigned s = (unsigned)__cvta_generic_to_shared(smem);
    asm volatile("cp.async.cg.shared.global [%0], [%1], 16;\n" :: "r"(s), "l"(gmem) : "memory");
}
__device__ __forceinline__ void cp_commit() {
    asm volatile("cp.async.commit_group;\n" ::: "memory");
}
__device__ __forceinline__ void cp_wait0() {
    asm volatile("cp.async.wait_group 0;\n" ::: "memory");
}

// ---------------------------------------------------------------------------
// Kernel 1: pack weights into compact, transposed, mask-gathered layout
// ---------------------------------------------------------------------------
__global__ void pack_kernel(const float* __restrict__ sW1, const float* __restrict__ sb1,
                            const float* __restrict__ sW2, const float* __restrict__ sb2,
                            const float* __restrict__ tW1, const float* __restrict__ tb1,
                            const float* __restrict__ tW2, const float* __restrict__ tb2,
                            const float* __restrict__ ans, const float* __restrict__ ant) {
    int ck = blockIdx.x;           // c*64 + k
    int k  = ck & 63;
    int p  = k & 1;                // masked dims: d%2 == k%2
    float* dst = g_packed + (size_t)ck * PK;
    const float* w1s = sW1 + (size_t)ck * 2048;
    const float* w2s = sW2 + (size_t)ck * 2048;
    const float* w1t = tW1 + (size_t)ck * 2048;
    const float* w2t = tW2 + (size_t)ck * 2048;

    for (int t = threadIdx.x; t < 1024; t += blockDim.x) {
        int j = t >> 4, i = t & 15;
        int di = 2 * i + p;          // masked input dim
        int du = 2 * i + 1 - p;      // unmasked output dim
        dst[O_W1S + t] = w1s[j * 32 + di];
        dst[O_W1T + t] = w1t[j * 32 + di];
        dst[O_W2S + t] = w2s[du * 64 + j];
        dst[O_W2T + t] = w2t[du * 64 + j];
    }
    for (int t = threadIdx.x; t < 64; t += blockDim.x) {
        dst[O_B1S + t] = sb1[ck * 64 + t];
        dst[O_B1T + t] = tb1[ck * 64 + t];
    }
    for (int t = threadIdx.x; t < 16; t += blockDim.x) {
        int du = 2 * t + 1 - p;
        dst[O_B2S + t] = sb2[ck * 32 + du];
        dst[O_B2T + t] = tb2[ck * 32 + du];
    }
    for (int t = threadIdx.x; t < 32; t += blockDim.x) {
        dst[O_ANE + t] = expf(-ans[ck * 32 + t]);
        dst[O_ANT + t] = ant[ck * 32 + t];
    }
    if (threadIdx.x == 0) {
        float s = 0.f;
        for (int d = 0; d < 32; d++) s += ans[ck * 32 + d];
        dst[O_ASUM] = s;
        for (int q = O_ASUM + 1; q < PK; q++) dst[q] = 0.f;
    }
}

// ---------------------------------------------------------------------------
// Kernel 2: the flow chain (dominant cost)
// ---------------------------------------------------------------------------
template <int P>
__device__ __forceinline__ void layer_step(const float* sw, float* z, float& ld) {
    ld -= sw[O_ASUM];
    // ActNorm inverse
#pragma unroll
    for (int d = 0; d < 32; d++) z[d] = (z[d] - sw[O_ANT + d]) * sw[O_ANE + d];

    float xm[16];
#pragma unroll
    for (int i = 0; i < 16; i++) xm[i] = z[2 * i + P];

    float sv[16], tv[16];
#pragma unroll
    for (int i = 0; i < 16; i++) { sv[i] = sw[O_B2S + i]; tv[i] = sw[O_B2T + i]; }

#pragma unroll 4
    for (int j = 0; j < 64; j++) {
        float w[16];
        // ----- s-net hidden unit j -----
#pragma unroll
        for (int q = 0; q < 4; q++)
            *reinterpret_cast<float4*>(&w[q * 4]) =
                *reinterpret_cast<const float4*>(sw + O_W1S + j * 16 + q * 4);
        float p0 = 0.f, p1 = 0.f, p2 = 0.f, p3 = 0.f;
#pragma unroll
        for (int i = 0; i < 4; i++) {
            p0 = fmaf(w[i],      xm[i],      p0);
            p1 = fmaf(w[4 + i],  xm[4 + i],  p1);
            p2 = fmaf(w[8 + i],  xm[8 + i],  p2);
            p3 = fmaf(w[12 + i], xm[12 + i], p3);
        }
        float hs = fmaxf(sw[O_B1S + j] + ((p0 + p1) + (p2 + p3)), 0.f);
#pragma unroll
        for (int q = 0; q < 4; q++)
            *reinterpret_cast<float4*>(&w[q * 4]) =
                *reinterpret_cast<const float4*>(sw + O_W2S + j * 16 + q * 4);
#pragma unroll
        for (int i = 0; i < 16; i++) sv[i] = fmaf(w[i], hs, sv[i]);

        // ----- t-net hidden unit j -----
#pragma unroll
        for (int q = 0; q < 4; q++)
            *reinterpret_cast<float4*>(&w[q * 4]) =
                *reinterpret_cast<const float4*>(sw + O_W1T + j * 16 + q * 4);
        p0 = p1 = p2 = p3 = 0.f;
#pragma unroll
        for (int i = 0; i < 4; i++) {
            p0 = fmaf(w[i],      xm[i],      p0);
            p1 = fmaf(w[4 + i],  xm[4 + i],  p1);
            p2 = fmaf(w[8 + i],  xm[8 + i],  p2);
            p3 = fmaf(w[12 + i], xm[12 + i], p3);
        }
        float ht = fmaxf(sw[O_B1T + j] + ((p0 + p1) + (p2 + p3)), 0.f);
#pragma unroll
        for (int q = 0; q < 4; q++)
            *reinterpret_cast<float4*>(&w[q * 4]) =
                *reinterpret_cast<const float4*>(sw + O_W2T + j * 16 + q * 4);
#pragma unroll
        for (int i = 0; i < 16; i++) tv[i] = fmaf(w[i], ht, tv[i]);
    }

    // Coupling inverse on unmasked dims
#pragma unroll
    for (int i = 0; i < 16; i++) {
        int d = 2 * i + 1 - P;
        z[d] = (z[d] - tv[i]) * __expf(-sv[i]);
        ld -= sv[i];
    }
}

__device__ __forceinline__ void prefetch_layer(float* dst, const float* src) {
    int t = threadIdx.x;
#pragma unroll
    for (int q = 0; q < 9; q++) {
        int idx = t + q * 128;          // 16B units; total PK/4 = 1088
        if (idx < PK / 4) cp_async16(dst + idx * 4, src + idx * 4);
    }
}

__global__ void __launch_bounds__(128, 1)
flow_kernel(const float* __restrict__ nodes, const float* __restrict__ loc,
            const float* __restrict__ lsc) {
    __shared__ __align__(16) float sw[2][PK];
    const int c = blockIdx.y;
    const int n = blockIdx.x * 128 + threadIdx.x;

    float z[32];
#pragma unroll
    for (int q = 0; q < 8; q++) {
        float4 v = *reinterpret_cast<const float4*>(nodes + n * 32 + q * 4);
        z[q * 4] = v.x; z[q * 4 + 1] = v.y; z[q * 4 + 2] = v.z; z[q * 4 + 3] = v.w;
    }
    float ld = 0.f;

    const float* gp = g_packed + (size_t)c * (KK * PK);
    prefetch_layer(sw[1], gp + 63 * PK);   // layer 63 -> buf (63&1)=1
    cp_commit();

    for (int it = 0; it < 64; it++) {
        const int k = 63 - it;
        const int b = k & 1;
        cp_wait0();
        __syncthreads();
        if (it < 63) prefetch_layer(sw[b ^ 1], gp + (k - 1) * PK);
        cp_commit();
        if (b) layer_step<1>(sw[b], z, ld);
        else   layer_step<0>(sw[b], z, ld);
        // no trailing sync needed: next iteration's top __syncthreads guards reuse
    }

    // DiagGaussian log prob
    float lq = ld - 29.40603306254953f;    // 0.5 * D * log(2*pi)
    const float* lc = loc + c * 32;
    const float* ls = lsc + c * 32;
#pragma unroll
    for (int d = 0; d < 32; d++) {
        float l = ls[d];
        float u = (z[d] - lc[d]) * __expf(-l);
        lq -= l + 0.5f * u * u;
    }
    g_logq[c * NN + n] = lq;
}

// ---------------------------------------------------------------------------
// Kernel 3: exp + per-component L1 row sums (with 1e-12 clamp!)
// ---------------------------------------------------------------------------
__global__ void rowsum_kernel() {
    int c = blockIdx.x;
    __shared__ float red[256];
    float s = 0.f;
    for (int n = threadIdx.x; n < NN; n += 256) {
        float e = expf(g_logq[c * NN + n]);
        g_E[n * CC + c] = e;
        s += e;
    }
    red[threadIdx.x] = s;
    __syncthreads();
    for (int w = 128; w > 0; w >>= 1) {
        if (threadIdx.x < w) red[threadIdx.x] += red[threadIdx.x + w];
        __syncthreads();
    }
    if (threadIdx.x == 0) g_den[c] = fmaxf(red[0], 1e-12f);
}

// ---------------------------------------------------------------------------
// Kernel 4: S = exp(S_unc) / sum(exp(S_unc))
// ---------------------------------------------------------------------------
__global__ void smat_kernel(const float* __restrict__ S_unc) {
    __shared__ float e[64];
    __shared__ float tot;
    int t = threadIdx.x;
    float v = expf(S_unc[t]);
    e[t] = v;
    __syncthreads();
    if (t == 0) {
        float s = 0.f;
        for (int i = 0; i < 64; i++) s += e[i];
        tot = s;
    }
    __syncthreads();
    g_S[t] = v / tot;
}

// ---------------------------------------------------------------------------
// Kernel 5: G = Bm normalized, A[j][c] = sum_c' S[c][c'] * G[j][c']
// ---------------------------------------------------------------------------
__global__ void ga_kernel() {
    __shared__ float sS[64];
    __shared__ float sden[8];
    if (threadIdx.x < 64) sS[threadIdx.x] = g_S[threadIdx.x];
    if (threadIdx.x < 8)  sden[threadIdx.x] = g_den[threadIdx.x];
    __syncthreads();
    int j = blockIdx.x * 256 + threadIdx.x;
    float g[8];
#pragma unroll
    for (int c = 0; c < 8; c++) g[c] = g_E[j * CC + c] / sden[c];
#pragma unroll
    for (int c = 0; c < 8; c++) g_G[j * CC + c] = g[c];
#pragma unroll
    for (int c = 0; c < 8; c++) {
        float a = 0.f;
#pragma unroll
        for (int c2 = 0; c2 < 8; c2++) a = fmaf(sS[c * 8 + c2], g[c2], a);
        g_A[j * CC + c] = a;
    }
}

// ---------------------------------------------------------------------------
// Kernel 6: out[i][j] = sum_c G[i][c] * A[j][c]   (rank-8, 64x64 tiles)
// ---------------------------------------------------------------------------
__global__ void __launch_bounds__(256) outer_kernel(float* __restrict__ out) {
    __shared__ float Gs[64][8];
    __shared__ float As[64][8];
    int i0 = blockIdx.y * 64, j0 = blockIdx.x * 64;
    int t = threadIdx.x;
    for (int q = t; q < 512; q += 256) {
        ((float*)Gs)[q] = g_G[i0 * 8 + q];
        ((float*)As)[q] = g_A[j0 * 8 + q];
    }
    __syncthreads();
    int tx = t & 15, ty = t >> 4;
    float gr[4][8], ar[4][8];
#pragma unroll
    for (int r = 0; r < 4; r++)
#pragma unroll
        for (int c = 0; c < 8; c++) {
            gr[r][c] = Gs[ty * 4 + r][c];
            ar[r][c] = As[tx * 4 + r][c];
        }
#pragma unroll
    for (int r = 0; r < 4; r++) {
        float4 o;
        float acc[4] = {0.f, 0.f, 0.f, 0.f};
#pragma unroll
        for (int c = 0; c < 8; c++) {
            acc[0] = fmaf(gr[r][c], ar[0][c], acc[0]);
            acc[1] = fmaf(gr[r][c], ar[1][c], acc[1]);
            acc[2] = fmaf(gr[r][c], ar[2][c], acc[2]);
            acc[3] = fmaf(gr[r][c], ar[3][c], acc[3]);
        }
        o.x = acc[0]; o.y = acc[1]; o.z = acc[2]; o.w = acc[3];
        *reinterpret_cast<float4*>(out + (size_t)(i0 + ty * 4 + r) * NN + j0 + tx * 4) = o;
    }
}

// ---------------------------------------------------------------------------
extern "C" void kernel_launch(void* const* d_in, const int* in_sizes, int n_in,
                              void* d_out, int out_size) {
    const float* nodes = (const float*)d_in[0];
    const float* sW1   = (const float*)d_in[1];
    const float* sb1   = (const float*)d_in[2];
    const float* sW2   = (const float*)d_in[3];
    const float* sb2   = (const float*)d_in[4];
    const float* tW1   = (const float*)d_in[5];
    const float* tb1   = (const float*)d_in[6];
    const float* tW2   = (const float*)d_in[7];
    const float* tb2   = (const float*)d_in[8];
    const float* ans   = (const float*)d_in[9];
    const float* ant   = (const float*)d_in[10];
    const float* loc   = (const float*)d_in[11];
    const float* lsc   = (const float*)d_in[12];
    const float* Sunc  = (const float*)d_in[13];
    float* out = (float*)d_out;

    pack_kernel<<<CC * KK, 256>>>(sW1, sb1, sW2, sb2, tW1, tb1, tW2, tb2, ans, ant);
    flow_kernel<<<dim3(NN / 128, CC), 128>>>(nodes, loc, lsc);
    rowsum_kernel<<<CC, 256>>>();
    smat_kernel<<<1, 64>>>(Sunc);
    ga_kernel<<<NN / 256, 256>>>();
    outer_kernel<<<dim3(NN / 64, NN / 64), 256>>>(out);
}

// round 2
// speedup vs baseline: 1.0660x; 1.0660x over previous
#include <cuda_runtime.h>
#include <cuda_bf16.h>
#include <cstdint>

// Problem constants
#define CC 8
#define KK 64
#define DD 32
#define NN 2048

// Packed per-(c,k) weight block layout (floats)
#define PK      4352
#define O_W1S   0      // [64][16]  W1s columns at masked dims
#define O_B1S   1024   // [64]
#define O_W2S   1088   // [64][16]  W2s transposed: [j][i] = W2[ud(i)][j]
#define O_B2S   2112   // [16]
#define O_W1T   2128
#define O_B1T   3152
#define O_W2T   3216
#define O_B2T   4240
#define O_ANE   4256   // [32] exp(-an_s)
#define O_ANB   4288   // [32] -an_t * exp(-an_s)
#define O_ASUM  4320   // sum(an_s)

typedef unsigned long long u64;

// Scratch (__device__ globals: allocation-free)
__device__ float g_packed[CC * KK * PK];   // ~8.9 MB
__device__ float g_logq[CC * NN];
__device__ float g_E[NN * CC];             // [n][c]
__device__ float g_G[NN * CC];
__device__ float g_A[NN * CC];
__device__ float g_den[CC];
__device__ float g_S[CC * CC];

// ---------------------------------------------------------------------------
// f32x2 packed-math helpers (Blackwell FFMA2 path)
// ---------------------------------------------------------------------------
__device__ __forceinline__ u64 fma2(u64 a, u64 b, u64 c) {
    u64 d;
    asm("fma.rn.f32x2 %0, %1, %2, %3;" : "=l"(d) : "l"(a), "l"(b), "l"(c));
    return d;
}
__device__ __forceinline__ u64 add2(u64 a, u64 b) {
    u64 d;
    asm("add.rn.f32x2 %0, %1, %2;" : "=l"(d) : "l"(a), "l"(b));
    return d;
}
__device__ __forceinline__ u64 packf2(float lo, float hi) {
    u64 d;
    asm("mov.b64 %0, {%1, %2};" : "=l"(d) : "f"(lo), "f"(hi));
    return d;
}
__device__ __forceinline__ float2 unpackf2(u64 v) {
    float2 r;
    asm("mov.b64 {%0, %1}, %2;" : "=f"(r.x), "=f"(r.y) : "l"(v));
    return r;
}

// ---------------------------------------------------------------------------
// cp.async helpers
// ---------------------------------------------------------------------------
__device__ __forceinline__ void cp_async16(void* smem, const void* gmem) {
    unsigned s = (unsigned)__cvta_generic_to_shared(smem);
    asm volatile("cp.async.cg.shared.global [%0], [%1], 16;\n" :: "r"(s), "l"(gmem) : "memory");
}
__device__ __forceinline__ void cp_commit() {
    asm volatile("cp.async.commit_group;\n" ::: "memory");
}
__device__ __forceinline__ void cp_wait0() {
    asm volatile("cp.async.wait_group 0;\n" ::: "memory");
}

// ---------------------------------------------------------------------------
// Kernel 1: pack weights into compact, transposed, mask-gathered layout
// ---------------------------------------------------------------------------
__global__ void pack_kernel(const float* __restrict__ sW1, const float* __restrict__ sb1,
                            const float* __restrict__ sW2, const float* __restrict__ sb2,
                            const float* __restrict__ tW1, const float* __restrict__ tb1,
                            const float* __restrict__ tW2, const float* __restrict__ tb2,
                            const float* __restrict__ ans, const float* __restrict__ ant) {
    int ck = blockIdx.x;           // c*64 + k
    int k  = ck & 63;
    int p  = k & 1;                // masked dims: d%2 == k%2
    float* dst = g_packed + (size_t)ck * PK;
    const float* w1s = sW1 + (size_t)ck * 2048;
    const float* w2s = sW2 + (size_t)ck * 2048;
    const float* w1t = tW1 + (size_t)ck * 2048;
    const float* w2t = tW2 + (size_t)ck * 2048;

    for (int t = threadIdx.x; t < 1024; t += blockDim.x) {
        int j = t >> 4, i = t & 15;
        int di = 2 * i + p;          // masked input dim
        int du = 2 * i + 1 - p;      // unmasked output dim
        dst[O_W1S + t] = w1s[j * 32 + di];
        dst[O_W1T + t] = w1t[j * 32 + di];
        dst[O_W2S + t] = w2s[du * 64 + j];
        dst[O_W2T + t] = w2t[du * 64 + j];
    }
    for (int t = threadIdx.x; t < 64; t += blockDim.x) {
        dst[O_B1S + t] = sb1[ck * 64 + t];
        dst[O_B1T + t] = tb1[ck * 64 + t];
    }
    for (int t = threadIdx.x; t < 16; t += blockDim.x) {
        int du = 2 * t + 1 - p;
        dst[O_B2S + t] = sb2[ck * 32 + du];
        dst[O_B2T + t] = tb2[ck * 32 + du];
    }
    for (int t = threadIdx.x; t < 32; t += blockDim.x) {
        float e = expf(-ans[ck * 32 + t]);
        dst[O_ANE + t] = e;
        dst[O_ANB + t] = -ant[ck * 32 + t] * e;   // z' = fma(z, e, -t*e)
    }
    if (threadIdx.x == 0) {
        float s = 0.f;
        for (int d = 0; d < 32; d++) s += ans[ck * 32 + d];
        dst[O_ASUM] = s;
        for (int q = O_ASUM + 1; q < PK; q++) dst[q] = 0.f;
    }
}

// ---------------------------------------------------------------------------
// Kernel 2: the flow chain (dominant cost) — packed f32x2 math
// ---------------------------------------------------------------------------
template <int P>
__device__ __forceinline__ void layer_step(const float* sw, float* z, float& ld) {
    ld -= sw[O_ASUM];
    // ActNorm inverse: z = z * exp(-s) + (-t*exp(-s))  — single FFMA per dim
#pragma unroll
    for (int d = 0; d < 32; d++) z[d] = fmaf(z[d], sw[O_ANE + d], sw[O_ANB + d]);

    // Masked inputs as 8 packed f32x2: pair q = (z[4q+P], z[4q+2+P])
    u64 xm[8];
#pragma unroll
    for (int q = 0; q < 8; q++) xm[q] = packf2(z[4 * q + P], z[4 * q + 2 + P]);

    // Accumulators: sv/tv as 8 f32x2 each, initialized from output biases
    u64 sv[8], tv[8];
#pragma unroll
    for (int q = 0; q < 4; q++) {
        ulonglong2 a = *reinterpret_cast<const ulonglong2*>(sw + O_B2S + q * 4);
        sv[2 * q] = a.x; sv[2 * q + 1] = a.y;
        ulonglong2 b = *reinterpret_cast<const ulonglong2*>(sw + O_B2T + q * 4);
        tv[2 * q] = b.x; tv[2 * q + 1] = b.y;
    }

#pragma unroll 4
    for (int j = 0; j < 64; j++) {
        // ---------------- s-net hidden unit j ----------------
        {
            ulonglong2 w0 = *reinterpret_cast<const ulonglong2*>(sw + O_W1S + j * 16);
            ulonglong2 w1 = *reinterpret_cast<const ulonglong2*>(sw + O_W1S + j * 16 + 4);
            ulonglong2 w2 = *reinterpret_cast<const ulonglong2*>(sw + O_W1S + j * 16 + 8);
            ulonglong2 w3 = *reinterpret_cast<const ulonglong2*>(sw + O_W1S + j * 16 + 12);
            u64 p0 = fma2(w0.x, xm[0], 0ull);
            u64 p1 = fma2(w0.y, xm[1], 0ull);
            p0 = fma2(w1.x, xm[2], p0);
            p1 = fma2(w1.y, xm[3], p1);
            p0 = fma2(w2.x, xm[4], p0);
            p1 = fma2(w2.y, xm[5], p1);
            p0 = fma2(w3.x, xm[6], p0);
            p1 = fma2(w3.y, xm[7], p1);
            float2 pp = unpackf2(add2(p0, p1));
            float hs = fmaxf(sw[O_B1S + j] + (pp.x + pp.y), 0.f);
            u64 hh = packf2(hs, hs);
            ulonglong2 v0 = *reinterpret_cast<const ulonglong2*>(sw + O_W2S + j * 16);
            ulonglong2 v1 = *reinterpret_cast<const ulonglong2*>(sw + O_W2S + j * 16 + 4);
            ulonglong2 v2 = *reinterpret_cast<const ulonglong2*>(sw + O_W2S + j * 16 + 8);
            ulonglong2 v3 = *reinterpret_cast<const ulonglong2*>(sw + O_W2S + j * 16 + 12);
            sv[0] = fma2(v0.x, hh, sv[0]); sv[1] = fma2(v0.y, hh, sv[1]);
            sv[2] = fma2(v1.x, hh, sv[2]); sv[3] = fma2(v1.y, hh, sv[3]);
            sv[4] = fma2(v2.x, hh, sv[4]); sv[5] = fma2(v2.y, hh, sv[5]);
            sv[6] = fma2(v3.x, hh, sv[6]); sv[7] = fma2(v3.y, hh, sv[7]);
        }
        // ---------------- t-net hidden unit j ----------------
        {
            ulonglong2 w0 = *reinterpret_cast<const ulonglong2*>(sw + O_W1T + j * 16);
            ulonglong2 w1 = *reinterpret_cast<const ulonglong2*>(sw + O_W1T + j * 16 + 4);
            ulonglong2 w2 = *reinterpret_cast<const ulonglong2*>(sw + O_W1T + j * 16 + 8);
            ulonglong2 w3 = *reinterpret_cast<const ulonglong2*>(sw + O_W1T + j * 16 + 12);
            u64 p0 = fma2(w0.x, xm[0], 0ull);
            u64 p1 = fma2(w0.y, xm[1], 0ull);
            p0 = fma2(w1.x, xm[2], p0);
            p1 = fma2(w1.y, xm[3], p1);
            p0 = fma2(w2.x, xm[4], p0);
            p1 = fma2(w2.y, xm[5], p1);
            p0 = fma2(w3.x, xm[6], p0);
            p1 = fma2(w3.y, xm[7], p1);
            float2 pp = unpackf2(add2(p0, p1));
            float ht = fmaxf(sw[O_B1T + j] + (pp.x + pp.y), 0.f);
            u64 hh = packf2(ht, ht);
            ulonglong2 v0 = *reinterpret_cast<const ulonglong2*>(sw + O_W2T + j * 16);
            ulonglong2 v1 = *reinterpret_cast<const ulonglong2*>(sw + O_W2T + j * 16 + 4);
            ulonglong2 v2 = *reinterpret_cast<const ulonglong2*>(sw + O_W2T + j * 16 + 8);
            ulonglong2 v3 = *reinterpret_cast<const ulonglong2*>(sw + O_W2T + j * 16 + 12);
            tv[0] = fma2(v0.x, hh, tv[0]); tv[1] = fma2(v0.y, hh, tv[1]);
            tv[2] = fma2(v1.x, hh, tv[2]); tv[3] = fma2(v1.y, hh, tv[3]);
            tv[4] = fma2(v2.x, hh, tv[4]); tv[5] = fma2(v2.y, hh, tv[5]);
            tv[6] = fma2(v3.x, hh, tv[6]); tv[7] = fma2(v3.y, hh, tv[7]);
        }
    }

    // Coupling inverse on unmasked dims.
    // sv pair q = (s_{2q}, s_{2q+1}); unmasked dim for i is 2i+1-P.
#pragma unroll
    for (int q = 0; q < 8; q++) {
        float2 s2 = unpackf2(sv[q]);
        float2 t2 = unpackf2(tv[q]);
        int d0 = 4 * q + 1 - P;
        int d1 = 4 * q + 3 - P;
        z[d0] = (z[d0] - t2.x) * __expf(-s2.x);
        z[d1] = (z[d1] - t2.y) * __expf(-s2.y);
        ld -= s2.x + s2.y;
    }
}

__device__ __forceinline__ void prefetch_layer(float* dst, const float* src) {
    int t = threadIdx.x;
#pragma unroll
    for (int q = 0; q < 9; q++) {
        int idx = t + q * 128;          // 16B units; total PK/4 = 1088
        if (idx < PK / 4) cp_async16(dst + idx * 4, src + idx * 4);
    }
}

__global__ void __launch_bounds__(128, 1)
flow_kernel(const float* __restrict__ nodes, const float* __restrict__ loc,
            const float* __restrict__ lsc) {
    __shared__ __align__(16) float sw[2][PK];
    const int c = blockIdx.y;
    const int n = blockIdx.x * 128 + threadIdx.x;

    float z[32];
#pragma unroll
    for (int q = 0; q < 8; q++) {
        float4 v = *reinterpret_cast<const float4*>(nodes + n * 32 + q * 4);
        z[q * 4] = v.x; z[q * 4 + 1] = v.y; z[q * 4 + 2] = v.z; z[q * 4 + 3] = v.w;
    }
    float ld = 0.f;

    const float* gp = g_packed + (size_t)c * (KK * PK);
    prefetch_layer(sw[1], gp + 63 * PK);   // layer 63 -> buf (63&1)=1
    cp_commit();

    for (int it = 0; it < 64; it++) {
        const int k = 63 - it;
        const int b = k & 1;
        cp_wait0();
        __syncthreads();
        if (it < 63) prefetch_layer(sw[b ^ 1], gp + (k - 1) * PK);
        cp_commit();
        if (b) layer_step<1>(sw[b], z, ld);
        else   layer_step<0>(sw[b], z, ld);
        // next iteration's top __syncthreads guards buffer reuse
    }

    // DiagGaussian log prob
    float lq = ld - 29.40603306254953f;    // 0.5 * D * log(2*pi)
    const float* lc = loc + c * 32;
    const float* ls = lsc + c * 32;
#pragma unroll
    for (int d = 0; d < 32; d++) {
        float l = ls[d];
        float u = (z[d] - lc[d]) * __expf(-l);
        lq -= l + 0.5f * u * u;
    }
    g_logq[c * NN + n] = lq;
}

// ---------------------------------------------------------------------------
// Kernel 3: exp + per-component L1 row sums (with 1e-12 clamp!)
// ---------------------------------------------------------------------------
__global__ void rowsum_kernel() {
    int c = blockIdx.x;
    __shared__ float red[256];
    float s = 0.f;
    for (int n = threadIdx.x; n < NN; n += 256) {
        float e = expf(g_logq[c * NN + n]);
        g_E[n * CC + c] = e;
        s += e;
    }
    red[threadIdx.x] = s;
    __syncthreads();
    for (int w = 128; w > 0; w >>= 1) {
        if (threadIdx.x < w) red[threadIdx.x] += red[threadIdx.x + w];
        __syncthreads();
    }
    if (threadIdx.x == 0) g_den[c] = fmaxf(red[0], 1e-12f);
}

// ---------------------------------------------------------------------------
// Kernel 4: S = exp(S_unc) / sum(exp(S_unc))
// ---------------------------------------------------------------------------
__global__ void smat_kernel(const float* __restrict__ S_unc) {
    __shared__ float e[64];
    __shared__ float tot;
    int t = threadIdx.x;
    float v = expf(S_unc[t]);
    e[t] = v;
    __syncthreads();
    if (t == 0) {
        float s = 0.f;
        for (int i = 0; i < 64; i++) s += e[i];
        tot = s;
    }
    __syncthreads();
    g_S[t] = v / tot;
}

// ---------------------------------------------------------------------------
// Kernel 5: G = Bm normalized, A[j][c] = sum_c' S[c][c'] * G[j][c']
// ---------------------------------------------------------------------------
__global__ void ga_kernel() {
    __shared__ float sS[64];
    __shared__ float sden[8];
    if (threadIdx.x < 64) sS[threadIdx.x] = g_S[threadIdx.x];
    if (threadIdx.x < 8)  sden[threadIdx.x] = g_den[threadIdx.x];
    __syncthreads();
    int j = blockIdx.x * 256 + threadIdx.x;
    float g[8];
#pragma unroll
    for (int c = 0; c < 8; c++) g[c] = g_E[j * CC + c] / sden[c];
#pragma unroll
    for (int c = 0; c < 8; c++) g_G[j * CC + c] = g[c];
#pragma unroll
    for (int c = 0; c < 8; c++) {
        float a = 0.f;
#pragma unroll
        for (int c2 = 0; c2 < 8; c2++) a = fmaf(sS[c * 8 + c2], g[c2], a);
        g_A[j * CC + c] = a;
    }
}

// ---------------------------------------------------------------------------
// Kernel 6: out[i][j] = sum_c G[i][c] * A[j][c]   (rank-8, 64x64 tiles)
// ---------------------------------------------------------------------------
__global__ void __launch_bounds__(256) outer_kernel(float* __restrict__ out) {
    __shared__ float Gs[64][8];
    __shared__ float As[64][8];
    int i0 = blockIdx.y * 64, j0 = blockIdx.x * 64;
    int t = threadIdx.x;
    for (int q = t; q < 512; q += 256) {
        ((float*)Gs)[q] = g_G[i0 * 8 + q];
        ((float*)As)[q] = g_A[j0 * 8 + q];
    }
    __syncthreads();
    int tx = t & 15, ty = t >> 4;
    float gr[4][8], ar[4][8];
#pragma unroll
    for (int r = 0; r < 4; r++)
#pragma unroll
        for (int c = 0; c < 8; c++) {
            gr[r][c] = Gs[ty * 4 + r][c];
            ar[r][c] = As[tx * 4 + r][c];
        }
#pragma unroll
    for (int r = 0; r < 4; r++) {
        float4 o;
        float acc[4] = {0.f, 0.f, 0.f, 0.f};
#pragma unroll
        for (int c = 0; c < 8; c++) {
            acc[0] = fmaf(gr[r][c], ar[0][c], acc[0]);
            acc[1] = fmaf(gr[r][c], ar[1][c], acc[1]);
            acc[2] = fmaf(gr[r][c], ar[2][c], acc[2]);
            acc[3] = fmaf(gr[r][c], ar[3][c], acc[3]);
        }
        o.x = acc[0]; o.y = acc[1]; o.z = acc[2]; o.w = acc[3];
        *reinterpret_cast<float4*>(out + (size_t)(i0 + ty * 4 + r) * NN + j0 + tx * 4) = o;
    }
}

// ---------------------------------------------------------------------------
extern "C" void kernel_launch(void* const* d_in, const int* in_sizes, int n_in,
                              void* d_out, int out_size) {
    const float* nodes = (const float*)d_in[0];
    const float* sW1   = (const float*)d_in[1];
    const float* sb1   = (const float*)d_in[2];
    const float* sW2   = (const float*)d_in[3];
    const float* sb2   = (const float*)d_in[4];
    const float* tW1   = (const float*)d_in[5];
    const float* tb1   = (const float*)d_in[6];
    const float* tW2   = (const float*)d_in[7];
    const float* tb2   = (const float*)d_in[8];
    const float* ans   = (const float*)d_in[9];
    const float* ant   = (const float*)d_in[10];
    const float* loc   = (const float*)d_in[11];
    const float* lsc   = (const float*)d_in[12];
    const float* Sunc  = (const float*)d_in[13];
    float* out = (float*)d_out;

    pack_kernel<<<CC * KK, 256>>>(sW1, sb1, sW2, sb2, tW1, tb1, tW2, tb2, ans, ant);
    flow_kernel<<<dim3(NN / 128, CC), 128>>>(nodes, loc, lsc);
    rowsum_kernel<<<CC, 256>>>();
    smat_kernel<<<1, 64>>>(Sunc);
    ga_kernel<<<NN / 256, 256>>>();
    outer_kernel<<<dim3(NN / 64, NN / 64), 256>>>(out);
}